// round 1
// baseline (speedup 1.0000x reference)
#include <cuda_runtime.h>
#include <math.h>

// Problem constants (fixed shapes)
#define Nn 10000
#define Ee 320000
#define Hh 128
#define H2 256
#define Lh 4
#define NG 64
#define NC 10
#define MSG_EPS 1e-7f

// ---------------- scratch (device globals; no allocation allowed) ----------------
__device__ float g_h[Nn * Hh];      // node state h
__device__ float g_u[Nn * Hh];      // agg + x (MLP input)
__device__ float g_r[Nn * Hh];      // relu(LN(h))
__device__ float g_z[Nn * H2];      // u @ W1 + b1
__device__ float g_hid[Nn * H2];    // relu(LN(z))
__device__ float g_pooled[NG * Hh];
__device__ int   g_cnt[Nn];
__device__ int   g_rowptr[Nn + 1];
__device__ int   g_pos[Nn];
__device__ int   g_peid[Ee];
__device__ int   g_psrc[Ee];

// ---------------- small utility kernels ----------------
__global__ void fill_i32(int* p, int v, int n) {
    int i = blockIdx.x * blockDim.x + threadIdx.x;
    if (i < n) p[i] = v;
}
__global__ void fill_f32(float* p, float v, int n) {
    int i = blockIdx.x * blockDim.x + threadIdx.x;
    if (i < n) p[i] = v;
}
__global__ void copy_i32(const int* a, int* b, int n) {
    int i = blockIdx.x * blockDim.x + threadIdx.x;
    if (i < n) b[i] = a[i];
}

// ---------------- CSR build ----------------
__global__ void hist_kernel(const int* __restrict__ dst, int* cnt) {
    int e = blockIdx.x * blockDim.x + threadIdx.x;
    if (e < Ee) atomicAdd(&cnt[dst[e]], 1);
}

__global__ __launch_bounds__(1024) void scan_kernel(const int* __restrict__ cnt, int* rowptr) {
    __shared__ int part[1024];
    const int CH = 10;  // 1024*10 = 10240 >= Nn
    int tid = threadIdx.x;
    int base = tid * CH;
    int loc[CH];
    int s = 0;
#pragma unroll
    for (int i = 0; i < CH; i++) {
        int idx = base + i;
        int v = (idx < Nn) ? cnt[idx] : 0;
        loc[i] = s;
        s += v;
    }
    part[tid] = s;
    __syncthreads();
    for (int off = 1; off < 1024; off <<= 1) {
        int v = (tid >= off) ? part[tid - off] : 0;
        __syncthreads();
        part[tid] += v;
        __syncthreads();
    }
    int pre = (tid > 0) ? part[tid - 1] : 0;
#pragma unroll
    for (int i = 0; i < CH; i++) {
        int idx = base + i;
        if (idx <= Nn) rowptr[idx] = pre + loc[i];
    }
}

__global__ void scatter_kernel(const int* __restrict__ src, const int* __restrict__ dst,
                               int* pos, int* peid, int* psrc) {
    int e = blockIdx.x * blockDim.x + threadIdx.x;
    if (e >= Ee) return;
    int d = dst[e];
    int slot = atomicAdd(&pos[d], 1);
    peid[slot] = e;
    psrc[slot] = src[e];
}

// ---------------- online scatter-softmax aggregation (warp per node) ----------------
__device__ __forceinline__ void softmax_upd(float v, float t, float& M, float& S, float& A) {
    float m = fmaxf(v, 0.f) + MSG_EPS;
    float l = m * t;
    if (l > M) {
        float sc = __expf(M - l);  // exp(-inf)=0 on first edge
        S = fmaf(S, sc, 1.f);
        A = fmaf(A, sc, m);
        M = l;
    } else {
        float ex = __expf(l - M);
        S += ex;
        A = fmaf(m, ex, A);
    }
}

__global__ void agg_kernel(const float* __restrict__ xin, const float* __restrict__ ea,
                           const int* __restrict__ rowptr, const int* __restrict__ peid,
                           const int* __restrict__ psrc, const float* __restrict__ tp,
                           int layer, float* __restrict__ u) {
    int w = (blockIdx.x * blockDim.x + threadIdx.x) >> 5;
    if (w >= Nn) return;
    int lane = threadIdx.x & 31;
    float t = tp[layer];
    int beg = rowptr[w], end = rowptr[w + 1];
    int f = lane * 4;
    float Mx = -3.4e38f, My = -3.4e38f, Mz = -3.4e38f, Mw = -3.4e38f;
    float Sx = 0.f, Sy = 0.f, Sz = 0.f, Sw = 0.f;
    float Ax = 0.f, Ay = 0.f, Az = 0.f, Aw = 0.f;
    for (int j = beg; j < end; j++) {
        int eid = __ldg(&peid[j]);
        int s = __ldg(&psrc[j]);
        float4 e4 = *reinterpret_cast<const float4*>(ea + (size_t)eid * Hh + f);
        float4 x4 = *reinterpret_cast<const float4*>(xin + (size_t)s * Hh + f);
        softmax_upd(x4.x + e4.x, t, Mx, Sx, Ax);
        softmax_upd(x4.y + e4.y, t, My, Sy, Ay);
        softmax_upd(x4.z + e4.z, t, Mz, Sz, Az);
        softmax_upd(x4.w + e4.w, t, Mw, Sw, Aw);
    }
    float4 xn = *reinterpret_cast<const float4*>(xin + (size_t)w * Hh + f);
    float4 o;
    if (end > beg) {
        o.x = Ax / Sx + xn.x;
        o.y = Ay / Sy + xn.y;
        o.z = Az / Sz + xn.z;
        o.w = Aw / Sw + xn.w;
    } else {
        o = xn;
    }
    *reinterpret_cast<float4*>(u + (size_t)w * Hh + f) = o;
}

// ---------------- GEMM: C[rows,COLS] = A[rows,K] @ W[K,COLS] + bias (+C if ACC) ----------------
template <int K, int COLS, bool ACC>
__global__ __launch_bounds__(512) void gemm_kernel(const float* __restrict__ A,
                                                   const float* __restrict__ W,
                                                   const float* __restrict__ bias,
                                                   float* __restrict__ C, int nrows) {
    constexpr int CG = COLS / 4;       // column groups (4 cols each)
    constexpr int RG = 512 / CG;       // row groups (4 rows each)
    constexpr int RT = RG * 4;         // rows per block tile
    constexpr int KC = (K < 128) ? K : 128;
    extern __shared__ float sm[];
    float* sW = sm;                    // K*COLS
    float* sA = sm + K * COLS;         // RT*KC
    int tid = threadIdx.x;
    for (int i = tid; i < K * COLS / 4; i += 512)
        reinterpret_cast<float4*>(sW)[i] = reinterpret_cast<const float4*>(W)[i];
    int row0 = blockIdx.x * RT;
    int cg = tid % CG, rg = tid / CG;
    float4 acc[4];
#pragma unroll
    for (int rr = 0; rr < 4; rr++) acc[rr] = make_float4(0.f, 0.f, 0.f, 0.f);

    for (int kk = 0; kk < K; kk += KC) {
        __syncthreads();
        for (int i = tid; i < RT * KC / 4; i += 512) {
            int r = i / (KC / 4), c = i % (KC / 4);
            int row = row0 + r;
            float4 v = make_float4(0.f, 0.f, 0.f, 0.f);
            if (row < nrows) v = reinterpret_cast<const float4*>(A + (size_t)row * K + kk)[c];
            reinterpret_cast<float4*>(sA)[i] = v;
        }
        __syncthreads();
#pragma unroll 8
        for (int k = 0; k < KC; k++) {
            float4 w4 = *reinterpret_cast<const float4*>(&sW[(kk + k) * COLS + cg * 4]);
            float a0 = sA[(rg * 4 + 0) * KC + k];
            float a1 = sA[(rg * 4 + 1) * KC + k];
            float a2 = sA[(rg * 4 + 2) * KC + k];
            float a3 = sA[(rg * 4 + 3) * KC + k];
            acc[0].x = fmaf(a0, w4.x, acc[0].x); acc[0].y = fmaf(a0, w4.y, acc[0].y);
            acc[0].z = fmaf(a0, w4.z, acc[0].z); acc[0].w = fmaf(a0, w4.w, acc[0].w);
            acc[1].x = fmaf(a1, w4.x, acc[1].x); acc[1].y = fmaf(a1, w4.y, acc[1].y);
            acc[1].z = fmaf(a1, w4.z, acc[1].z); acc[1].w = fmaf(a1, w4.w, acc[1].w);
            acc[2].x = fmaf(a2, w4.x, acc[2].x); acc[2].y = fmaf(a2, w4.y, acc[2].y);
            acc[2].z = fmaf(a2, w4.z, acc[2].z); acc[2].w = fmaf(a2, w4.w, acc[2].w);
            acc[3].x = fmaf(a3, w4.x, acc[3].x); acc[3].y = fmaf(a3, w4.y, acc[3].y);
            acc[3].z = fmaf(a3, w4.z, acc[3].z); acc[3].w = fmaf(a3, w4.w, acc[3].w);
        }
    }
    float4 b4 = reinterpret_cast<const float4*>(bias)[cg];
#pragma unroll
    for (int rr = 0; rr < 4; rr++) {
        int row = row0 + rg * 4 + rr;
        if (row < nrows) {
            float4 o = acc[rr];
            o.x += b4.x; o.y += b4.y; o.z += b4.z; o.w += b4.w;
            float4* cp = reinterpret_cast<float4*>(C + (size_t)row * COLS) + cg;
            if (ACC) {
                float4 old = *cp;
                o.x += old.x; o.y += old.y; o.z += old.z; o.w += old.w;
            }
            *cp = o;
        }
    }
}

// ---------------- LayerNorm + ReLU (warp per node) ----------------
template <int Wd>
__global__ void lnrelu_kernel(const float* __restrict__ X, const float* __restrict__ g,
                              const float* __restrict__ b, float* __restrict__ Y, int nrows) {
    int w = (blockIdx.x * blockDim.x + threadIdx.x) >> 5;
    if (w >= nrows) return;
    int lane = threadIdx.x & 31;
    constexpr int P = Wd / 128;
    float4 v[P];
    const float* xr = X + (size_t)w * Wd;
    float s = 0.f, s2 = 0.f;
#pragma unroll
    for (int p = 0; p < P; p++) {
        v[p] = reinterpret_cast<const float4*>(xr + p * 128)[lane];
        s += v[p].x + v[p].y + v[p].z + v[p].w;
        s2 += v[p].x * v[p].x + v[p].y * v[p].y + v[p].z * v[p].z + v[p].w * v[p].w;
    }
#pragma unroll
    for (int o = 16; o > 0; o >>= 1) {
        s += __shfl_xor_sync(0xffffffffu, s, o);
        s2 += __shfl_xor_sync(0xffffffffu, s2, o);
    }
    float mu = s * (1.f / Wd);
    float var = s2 * (1.f / Wd) - mu * mu;
    float inv = rsqrtf(var + 1e-5f);
    float* yr = Y + (size_t)w * Wd;
#pragma unroll
    for (int p = 0; p < P; p++) {
        float4 gv = reinterpret_cast<const float4*>(g + p * 128)[lane];
        float4 bv = reinterpret_cast<const float4*>(b + p * 128)[lane];
        float4 o;
        o.x = fmaxf((v[p].x - mu) * inv * gv.x + bv.x, 0.f);
        o.y = fmaxf((v[p].y - mu) * inv * gv.y + bv.y, 0.f);
        o.z = fmaxf((v[p].z - mu) * inv * gv.z + bv.z, 0.f);
        o.w = fmaxf((v[p].w - mu) * inv * gv.w + bv.w, 0.f);
        reinterpret_cast<float4*>(yr + p * 128)[lane] = o;
    }
}

// ---------------- global_add_pool ----------------
__global__ void pool_kernel(const float* __restrict__ r, const int* __restrict__ batch,
                            float* pooled) {
    int w = (blockIdx.x * blockDim.x + threadIdx.x) >> 5;
    if (w >= Nn) return;
    int lane = threadIdx.x & 31;
    int gidx = batch[w];
    float4 v = *reinterpret_cast<const float4*>(r + (size_t)w * Hh + lane * 4);
    float* dp = pooled + gidx * Hh + lane * 4;
    atomicAdd(dp + 0, v.x);
    atomicAdd(dp + 1, v.y);
    atomicAdd(dp + 2, v.z);
    atomicAdd(dp + 3, v.w);
}

// ---------------- classifier + output assembly: out = [logits(64x10), pooled(64x128)] ----------------
__global__ void final_kernel(const float* __restrict__ pooled, const float* __restrict__ linW,
                             const float* __restrict__ linb, float* __restrict__ out) {
    int idx = blockIdx.x * blockDim.x + threadIdx.x;
    int total = blockDim.x * gridDim.x;
    if (idx < NG * NC) {
        int gi = idx / NC, c = idx % NC;
        float sum = linb[c];
#pragma unroll 8
        for (int k = 0; k < Hh; k++) sum = fmaf(pooled[gi * Hh + k], linW[k * NC + c], sum);
        out[idx] = sum;
    }
    for (int i = idx; i < NG * Hh; i += total) out[NG * NC + i] = pooled[i];
}

// ---------------- launch ----------------
extern "C" void kernel_launch(void* const* d_in, const int* in_sizes, int n_in,
                              void* d_out, int out_size) {
    const float* x    = (const float*)d_in[0];
    const float* ea   = (const float*)d_in[1];
    const float* encW = (const float*)d_in[2];
    const float* encB = (const float*)d_in[3];
    const float* tp   = (const float*)d_in[4];
    const float* W1   = (const float*)d_in[5];
    const float* b1   = (const float*)d_in[6];
    const float* mg   = (const float*)d_in[7];
    const float* mb   = (const float*)d_in[8];
    const float* W2   = (const float*)d_in[9];
    const float* b2   = (const float*)d_in[10];
    const float* lg   = (const float*)d_in[11];
    const float* lb   = (const float*)d_in[12];
    const float* linW = (const float*)d_in[13];
    const float* linB = (const float*)d_in[14];
    const int*   eidx = (const int*)d_in[15];
    const int*   batch= (const int*)d_in[16];
    float* out = (float*)d_out;

    float *ph, *pu, *pr, *pz, *phid, *ppool;
    int *pcnt, *prow, *ppos, *ppeid, *ppsrc;
    cudaGetSymbolAddress((void**)&ph, g_h);
    cudaGetSymbolAddress((void**)&pu, g_u);
    cudaGetSymbolAddress((void**)&pr, g_r);
    cudaGetSymbolAddress((void**)&pz, g_z);
    cudaGetSymbolAddress((void**)&phid, g_hid);
    cudaGetSymbolAddress((void**)&ppool, g_pooled);
    cudaGetSymbolAddress((void**)&pcnt, g_cnt);
    cudaGetSymbolAddress((void**)&prow, g_rowptr);
    cudaGetSymbolAddress((void**)&ppos, g_pos);
    cudaGetSymbolAddress((void**)&ppeid, g_peid);
    cudaGetSymbolAddress((void**)&ppsrc, g_psrc);

    const int smem_enc = 128 * 128 * 4 + 64 * 128 * 4;   // 98304
    const int smem_g1  = 128 * 256 * 4 + 32 * 128 * 4;   // 147456
    const int smem_g2  = 256 * 128 * 4 + 64 * 128 * 4;   // 163840
    cudaFuncSetAttribute(gemm_kernel<128, 128, false>, cudaFuncAttributeMaxDynamicSharedMemorySize, smem_enc);
    cudaFuncSetAttribute(gemm_kernel<128, 256, false>, cudaFuncAttributeMaxDynamicSharedMemorySize, smem_g1);
    cudaFuncSetAttribute(gemm_kernel<256, 128, false>, cudaFuncAttributeMaxDynamicSharedMemorySize, smem_g2);
    cudaFuncSetAttribute(gemm_kernel<256, 128, true>,  cudaFuncAttributeMaxDynamicSharedMemorySize, smem_g2);

    const int* srcp = eidx;
    const int* dstp = eidx + Ee;

    // CSR build (by destination node)
    fill_i32<<<(Nn + 255) / 256, 256>>>(pcnt, 0, Nn);
    hist_kernel<<<(Ee + 255) / 256, 256>>>(dstp, pcnt);
    scan_kernel<<<1, 1024>>>(pcnt, prow);
    copy_i32<<<(Nn + 255) / 256, 256>>>(prow, ppos, Nn);
    scatter_kernel<<<(Ee + 255) / 256, 256>>>(srcp, dstp, ppos, ppeid, ppsrc);

    // encoder
    gemm_kernel<128, 128, false><<<157, 512, smem_enc>>>(x, encW, encB, ph, Nn);

    for (int i = 0; i < Lh; i++) {
        const float* xin = ph;
        if (i > 0) {
            lnrelu_kernel<128><<<1250, 256>>>(ph, lg + i * Hh, lb + i * Hh, pr, Nn);
            xin = pr;
        }
        agg_kernel<<<1250, 256>>>(xin, ea, prow, ppeid, ppsrc, tp, i, pu);
        gemm_kernel<128, 256, false><<<313, 512, smem_g1>>>(pu, W1 + (size_t)i * Hh * H2, b1 + i * H2, pz, Nn);
        lnrelu_kernel<256><<<1250, 256>>>(pz, mg + i * H2, mb + i * H2, phid, Nn);
        if (i == 0)
            gemm_kernel<256, 128, false><<<157, 512, smem_g2>>>(phid, W2 + (size_t)i * H2 * Hh, b2 + i * Hh, ph, Nn);
        else
            gemm_kernel<256, 128, true><<<157, 512, smem_g2>>>(phid, W2 + (size_t)i * H2 * Hh, b2 + i * Hh, ph, Nn);
    }

    // final act(norm(x)) with layer-0 LN params, pool, classify
    lnrelu_kernel<128><<<1250, 256>>>(ph, lg, lb, pr, Nn);
    fill_f32<<<(NG * Hh + 255) / 256, 256>>>(ppool, 0.f, NG * Hh);
    pool_kernel<<<1250, 256>>>(pr, batch, ppool);
    final_kernel<<<36, 256>>>(ppool, linW, linB, out);
}

// round 2
// speedup vs baseline: 1.1028x; 1.1028x over previous
#include <cuda_runtime.h>
#include <math.h>

// Problem constants (fixed shapes)
#define Nn 10000
#define Ee 320000
#define Hh 128
#define H2 256
#define Lh 4
#define NG 64
#define NC 10
#define MSG_EPS 1e-7f

// ---------------- scratch (device globals; no allocation allowed) ----------------
__device__ float g_h[Nn * Hh];      // node state h (residual stream)
__device__ float g_u[Nn * Hh];      // agg + x (MLP input)
__device__ float g_r[Nn * Hh];      // relu(LN(h)) for next layer / final
__device__ float g_hid[Nn * H2];    // relu(LN(u @ W1 + b1))
__device__ float g_pooled[NG * Hh];
__device__ int   g_cnt[Nn];
__device__ int   g_rowptr[Nn + 1];
__device__ int   g_pos[Nn];
__device__ int2  g_pe[Ee];          // (edge_id, src) packed, CSR order by dst

// ---------------- small utility kernels ----------------
__global__ void fill_i32(int* p, int v, int n) {
    int i = blockIdx.x * blockDim.x + threadIdx.x;
    if (i < n) p[i] = v;
}
__global__ void fill_f32(float* p, float v, int n) {
    int i = blockIdx.x * blockDim.x + threadIdx.x;
    if (i < n) p[i] = v;
}

// ---------------- CSR build ----------------
__global__ void hist_kernel(const int* __restrict__ dst, int* cnt) {
    int e = blockIdx.x * blockDim.x + threadIdx.x;
    if (e < Ee) atomicAdd(&cnt[dst[e]], 1);
}

__global__ __launch_bounds__(1024) void scan_kernel(const int* __restrict__ cnt,
                                                    int* rowptr, int* pos) {
    __shared__ int part[1024];
    const int CH = 10;  // 1024*10 = 10240 >= Nn
    int tid = threadIdx.x;
    int base = tid * CH;
    int loc[CH];
    int s = 0;
#pragma unroll
    for (int i = 0; i < CH; i++) {
        int idx = base + i;
        int v = (idx < Nn) ? cnt[idx] : 0;
        loc[i] = s;
        s += v;
    }
    part[tid] = s;
    __syncthreads();
    for (int off = 1; off < 1024; off <<= 1) {
        int v = (tid >= off) ? part[tid - off] : 0;
        __syncthreads();
        part[tid] += v;
        __syncthreads();
    }
    int pre = (tid > 0) ? part[tid - 1] : 0;
#pragma unroll
    for (int i = 0; i < CH; i++) {
        int idx = base + i;
        int v = pre + loc[i];
        if (idx <= Nn) rowptr[idx] = v;
        if (idx < Nn) pos[idx] = v;
    }
}

__global__ void scatter_kernel(const int* __restrict__ src, const int* __restrict__ dst,
                               int* pos, int2* pe) {
    int e = blockIdx.x * blockDim.x + threadIdx.x;
    if (e >= Ee) return;
    int d = dst[e];
    int slot = atomicAdd(&pos[d], 1);
    pe[slot] = make_int2(e, src[e]);
}

// ---------------- aggregation: max-free online scatter-softmax (warp per node) ----
// m = relu(x_j + e) + eps in [eps, ~15]; t = 1 => exp(m*t) <= ~3e6, no overflow.
__global__ void agg_kernel(const float* __restrict__ xin, const float* __restrict__ ea,
                           const int* __restrict__ rowptr, const int2* __restrict__ pe,
                           const float* __restrict__ tp, int layer, float* __restrict__ u) {
    int w = (blockIdx.x * blockDim.x + threadIdx.x) >> 5;
    if (w >= Nn) return;
    int lane = threadIdx.x & 31;
    float t = tp[layer];
    int beg = rowptr[w], end = rowptr[w + 1];
    int f = lane * 4;
    float Sx = 0.f, Sy = 0.f, Sz = 0.f, Sw = 0.f;
    float Ax = 0.f, Ay = 0.f, Az = 0.f, Aw = 0.f;
#pragma unroll 2
    for (int j = beg; j < end; j++) {
        int2 p = __ldg(&pe[j]);
        float4 e4 = __ldg(reinterpret_cast<const float4*>(ea + (size_t)p.x * Hh + f));
        float4 x4 = __ldg(reinterpret_cast<const float4*>(xin + (size_t)p.y * Hh + f));
        float mx = fmaxf(x4.x + e4.x, 0.f) + MSG_EPS;
        float my = fmaxf(x4.y + e4.y, 0.f) + MSG_EPS;
        float mz = fmaxf(x4.z + e4.z, 0.f) + MSG_EPS;
        float mw = fmaxf(x4.w + e4.w, 0.f) + MSG_EPS;
        float exx = __expf(mx * t), exy = __expf(my * t);
        float exz = __expf(mz * t), exw = __expf(mw * t);
        Sx += exx; Sy += exy; Sz += exz; Sw += exw;
        Ax = fmaf(mx, exx, Ax); Ay = fmaf(my, exy, Ay);
        Az = fmaf(mz, exz, Az); Aw = fmaf(mw, exw, Aw);
    }
    float4 xn = *reinterpret_cast<const float4*>(xin + (size_t)w * Hh + f);
    float4 o;
    if (end > beg) {
        o.x = Ax / Sx + xn.x;
        o.y = Ay / Sy + xn.y;
        o.z = Az / Sz + xn.z;
        o.w = Aw / Sw + xn.w;
    } else {
        o = xn;
    }
    *reinterpret_cast<float4*>(u + (size_t)w * Hh + f) = o;
}

// ---------------- GEMM with fused epilogues ----------------
// EPI 0: C = A@W + bias
// EPI 1: C = relu(LN(A@W + bias; g,b))
// EPI 2: h = (ACC ? C : 0) + A@W + bias; C = h; Y = relu(LN(h; g,b))
// Tile: 32 rows x COLS, 512 threads, whole W in smem (K x COLS), whole A tile in smem.
template <int K, int COLS, int RPT, int EPI, bool ACC>
__global__ __launch_bounds__(512) void gemm_kernel(const float* __restrict__ A,
                                                   const float* __restrict__ W,
                                                   const float* __restrict__ bias,
                                                   const float* __restrict__ lng,
                                                   const float* __restrict__ lnb,
                                                   float* __restrict__ C,
                                                   float* __restrict__ Y, int nrows) {
    constexpr int CG = COLS / 4;       // column groups (4 cols each)
    constexpr int RG = 512 / CG;       // row groups
    constexpr int RT = RG * RPT;       // rows per block tile (=32)
    extern __shared__ float sm[];
    float* sW = sm;                    // K*COLS
    float* sA = sm + K * COLS;         // RT*K, row-major
    __shared__ float red[RT][2][2];    // per-row {s,s2} per warp-half (EPI1)

    int tid = threadIdx.x;
    int row0 = blockIdx.x * RT;
    for (int i = tid; i < K * COLS / 4; i += 512)
        reinterpret_cast<float4*>(sW)[i] = reinterpret_cast<const float4*>(W)[i];
    for (int i = tid; i < RT * K / 4; i += 512) {
        int r = i / (K / 4), c = i % (K / 4);
        int row = row0 + r;
        float4 v = make_float4(0.f, 0.f, 0.f, 0.f);
        if (row < nrows) v = reinterpret_cast<const float4*>(A + (size_t)row * K)[c];
        reinterpret_cast<float4*>(sA)[i] = v;
    }
    __syncthreads();

    int cg = tid % CG, rg = tid / CG;
    float4 acc[RPT];
#pragma unroll
    for (int rr = 0; rr < RPT; rr++) acc[rr] = make_float4(0.f, 0.f, 0.f, 0.f);

#pragma unroll 8
    for (int k = 0; k < K; k++) {
        float4 w4 = *reinterpret_cast<const float4*>(&sW[k * COLS + cg * 4]);
#pragma unroll
        for (int rr = 0; rr < RPT; rr++) {
            float a = sA[(rg * RPT + rr) * K + k];
            acc[rr].x = fmaf(a, w4.x, acc[rr].x);
            acc[rr].y = fmaf(a, w4.y, acc[rr].y);
            acc[rr].z = fmaf(a, w4.z, acc[rr].z);
            acc[rr].w = fmaf(a, w4.w, acc[rr].w);
        }
    }

    float4 b4 = reinterpret_cast<const float4*>(bias)[cg];
#pragma unroll
    for (int rr = 0; rr < RPT; rr++) {
        acc[rr].x += b4.x; acc[rr].y += b4.y; acc[rr].z += b4.z; acc[rr].w += b4.w;
    }

    if (EPI == 0) {
#pragma unroll
        for (int rr = 0; rr < RPT; rr++) {
            int row = row0 + rg * RPT + rr;
            if (row < nrows)
                reinterpret_cast<float4*>(C + (size_t)row * COLS)[cg] = acc[rr];
        }
        return;
    }

    if (EPI == 2) {
        // residual add (h stream), then LN over COLS=128 within one warp
        float4 gv = reinterpret_cast<const float4*>(lng)[cg];
        float4 bv = reinterpret_cast<const float4*>(lnb)[cg];
#pragma unroll
        for (int rr = 0; rr < RPT; rr++) {
            int row = row0 + rg * RPT + rr;
            float4 h = acc[rr];
            if (ACC && row < nrows) {
                float4 old = reinterpret_cast<const float4*>(C + (size_t)row * COLS)[cg];
                h.x += old.x; h.y += old.y; h.z += old.z; h.w += old.w;
            }
            float s = h.x + h.y + h.z + h.w;
            float s2 = h.x * h.x + h.y * h.y + h.z * h.z + h.w * h.w;
#pragma unroll
            for (int o = 16; o > 0; o >>= 1) {
                s += __shfl_xor_sync(0xffffffffu, s, o);
                s2 += __shfl_xor_sync(0xffffffffu, s2, o);
            }
            float mu = s * (1.f / COLS);
            float var = s2 * (1.f / COLS) - mu * mu;
            float inv = rsqrtf(var + 1e-5f);
            float4 y;
            y.x = fmaxf((h.x - mu) * inv * gv.x + bv.x, 0.f);
            y.y = fmaxf((h.y - mu) * inv * gv.y + bv.y, 0.f);
            y.z = fmaxf((h.z - mu) * inv * gv.z + bv.z, 0.f);
            y.w = fmaxf((h.w - mu) * inv * gv.w + bv.w, 0.f);
            if (row < nrows) {
                reinterpret_cast<float4*>(C + (size_t)row * COLS)[cg] = h;
                reinterpret_cast<float4*>(Y + (size_t)row * COLS)[cg] = y;
            }
        }
        return;
    }

    // EPI == 1: LN over COLS=256, row spans 2 warps (CG=64)
    {
        int lane = tid & 31;
        int half = (tid >> 5) & 1;  // which warp of the rg pair
#pragma unroll
        for (int rr = 0; rr < RPT; rr++) {
            float s = acc[rr].x + acc[rr].y + acc[rr].z + acc[rr].w;
            float s2 = acc[rr].x * acc[rr].x + acc[rr].y * acc[rr].y +
                       acc[rr].z * acc[rr].z + acc[rr].w * acc[rr].w;
#pragma unroll
            for (int o = 16; o > 0; o >>= 1) {
                s += __shfl_xor_sync(0xffffffffu, s, o);
                s2 += __shfl_xor_sync(0xffffffffu, s2, o);
            }
            if (lane == 0) {
                int ri = rg * RPT + rr;
                red[ri][half][0] = s;
                red[ri][half][1] = s2;
            }
        }
        __syncthreads();
        float4 gv = reinterpret_cast<const float4*>(lng)[cg];
        float4 bv = reinterpret_cast<const float4*>(lnb)[cg];
#pragma unroll
        for (int rr = 0; rr < RPT; rr++) {
            int ri = rg * RPT + rr;
            float s = red[ri][0][0] + red[ri][1][0];
            float s2 = red[ri][0][1] + red[ri][1][1];
            float mu = s * (1.f / COLS);
            float var = s2 * (1.f / COLS) - mu * mu;
            float inv = rsqrtf(var + 1e-5f);
            float4 y;
            y.x = fmaxf((acc[rr].x - mu) * inv * gv.x + bv.x, 0.f);
            y.y = fmaxf((acc[rr].y - mu) * inv * gv.y + bv.y, 0.f);
            y.z = fmaxf((acc[rr].z - mu) * inv * gv.z + bv.z, 0.f);
            y.w = fmaxf((acc[rr].w - mu) * inv * gv.w + bv.w, 0.f);
            int row = row0 + ri;
            if (row < nrows)
                reinterpret_cast<float4*>(C + (size_t)row * COLS)[cg] = y;
        }
    }
}

// ---------------- global_add_pool ----------------
__global__ void pool_kernel(const float* __restrict__ r, const int* __restrict__ batch,
                            float* pooled) {
    int w = (blockIdx.x * blockDim.x + threadIdx.x) >> 5;
    if (w >= Nn) return;
    int lane = threadIdx.x & 31;
    int gidx = batch[w];
    float4 v = *reinterpret_cast<const float4*>(r + (size_t)w * Hh + lane * 4);
    float* dp = pooled + gidx * Hh + lane * 4;
    atomicAdd(dp + 0, v.x);
    atomicAdd(dp + 1, v.y);
    atomicAdd(dp + 2, v.z);
    atomicAdd(dp + 3, v.w);
}

// ---------------- classifier + output assembly ----------------
__global__ void final_kernel(const float* __restrict__ pooled, const float* __restrict__ linW,
                             const float* __restrict__ linb, float* __restrict__ out) {
    int idx = blockIdx.x * blockDim.x + threadIdx.x;
    int total = blockDim.x * gridDim.x;
    if (idx < NG * NC) {
        int gi = idx / NC, c = idx % NC;
        float sum = linb[c];
#pragma unroll 8
        for (int k = 0; k < Hh; k++) sum = fmaf(pooled[gi * Hh + k], linW[k * NC + c], sum);
        out[idx] = sum;
    }
    for (int i = idx; i < NG * Hh; i += total) out[NG * NC + i] = pooled[i];
}

// ---------------- launch ----------------
extern "C" void kernel_launch(void* const* d_in, const int* in_sizes, int n_in,
                              void* d_out, int out_size) {
    const float* x    = (const float*)d_in[0];
    const float* ea   = (const float*)d_in[1];
    const float* encW = (const float*)d_in[2];
    const float* encB = (const float*)d_in[3];
    const float* tp   = (const float*)d_in[4];
    const float* W1   = (const float*)d_in[5];
    const float* b1   = (const float*)d_in[6];
    const float* mg   = (const float*)d_in[7];
    const float* mb   = (const float*)d_in[8];
    const float* W2   = (const float*)d_in[9];
    const float* b2   = (const float*)d_in[10];
    const float* lg   = (const float*)d_in[11];
    const float* lb   = (const float*)d_in[12];
    const float* linW = (const float*)d_in[13];
    const float* linB = (const float*)d_in[14];
    const int*   eidx = (const int*)d_in[15];
    const int*   batch= (const int*)d_in[16];
    float* out = (float*)d_out;

    float *ph, *pu, *pr, *phid, *ppool;
    int *pcnt, *prow, *ppos;
    int2* ppe;
    cudaGetSymbolAddress((void**)&ph, g_h);
    cudaGetSymbolAddress((void**)&pu, g_u);
    cudaGetSymbolAddress((void**)&pr, g_r);
    cudaGetSymbolAddress((void**)&phid, g_hid);
    cudaGetSymbolAddress((void**)&ppool, g_pooled);
    cudaGetSymbolAddress((void**)&pcnt, g_cnt);
    cudaGetSymbolAddress((void**)&prow, g_rowptr);
    cudaGetSymbolAddress((void**)&ppos, g_pos);
    cudaGetSymbolAddress((void**)&ppe, g_pe);

    // smem: sW + sA (+ static red)
    const int smem_enc = (128 * 128 + 32 * 128) * 4;   // 80 KB
    const int smem_g1  = (128 * 256 + 32 * 128) * 4;   // 144 KB
    const int smem_g2  = (256 * 128 + 32 * 256) * 4;   // 160 KB
    cudaFuncSetAttribute((const void*)gemm_kernel<128, 128, 2, 0, false>,
                         cudaFuncAttributeMaxDynamicSharedMemorySize, smem_enc);
    cudaFuncSetAttribute((const void*)gemm_kernel<128, 256, 4, 1, false>,
                         cudaFuncAttributeMaxDynamicSharedMemorySize, smem_g1);
    cudaFuncSetAttribute((const void*)gemm_kernel<256, 128, 2, 2, false>,
                         cudaFuncAttributeMaxDynamicSharedMemorySize, smem_g2);
    cudaFuncSetAttribute((const void*)gemm_kernel<256, 128, 2, 2, true>,
                         cudaFuncAttributeMaxDynamicSharedMemorySize, smem_g2);

    const int* srcp = eidx;
    const int* dstp = eidx + Ee;
    const int GTILES = (Nn + 31) / 32;  // 313

    // CSR build (by destination node)
    fill_i32<<<(Nn + 255) / 256, 256>>>(pcnt, 0, Nn);
    hist_kernel<<<(Ee + 255) / 256, 256>>>(dstp, pcnt);
    scan_kernel<<<1, 1024>>>(pcnt, prow, ppos);
    scatter_kernel<<<(Ee + 255) / 256, 256>>>(srcp, dstp, ppos, ppe);

    // encoder: h = x @ encW + encB
    gemm_kernel<128, 128, 2, 0, false><<<GTILES, 512, smem_enc>>>(
        x, encW, encB, nullptr, nullptr, ph, nullptr, Nn);

    for (int i = 0; i < Lh; i++) {
        const float* xin = (i == 0) ? ph : pr;
        agg_kernel<<<1250, 256>>>(xin, ea, prow, ppe, tp, i, pu);
        // hid = relu(LN(u @ W1 + b1))
        gemm_kernel<128, 256, 4, 1, false><<<GTILES, 512, smem_g1>>>(
            pu, W1 + (size_t)i * Hh * H2, b1 + (size_t)i * H2,
            mg + (size_t)i * H2, mb + (size_t)i * H2, phid, nullptr, Nn);
        // h (+)= hid @ W2 + b2 ; r = relu(LN(h; next layer's params))
        int nl = (i < Lh - 1) ? (i + 1) : 0;
        if (i == 0)
            gemm_kernel<256, 128, 2, 2, false><<<GTILES, 512, smem_g2>>>(
                phid, W2 + (size_t)i * H2 * Hh, b2 + (size_t)i * Hh,
                lg + (size_t)nl * Hh, lb + (size_t)nl * Hh, ph, pr, Nn);
        else
            gemm_kernel<256, 128, 2, 2, true><<<GTILES, 512, smem_g2>>>(
                phid, W2 + (size_t)i * H2 * Hh, b2 + (size_t)i * Hh,
                lg + (size_t)nl * Hh, lb + (size_t)nl * Hh, ph, pr, Nn);
    }

    // pr already holds relu(LN(h; lg[0], lb[0]))
    fill_f32<<<(NG * Hh + 255) / 256, 256>>>(ppool, 0.f, NG * Hh);
    pool_kernel<<<1250, 256>>>(pr, batch, ppool);
    final_kernel<<<36, 256>>>(ppool, linW, linB, out);
}

// round 3
// speedup vs baseline: 1.4601x; 1.3241x over previous
#include <cuda_runtime.h>
#include <math.h>

// Problem constants (fixed shapes)
#define Nn 10000
#define Ee 320000
#define Hh 128
#define H2 256
#define Lh 4
#define NG 64
#define NC 10
#define MSG_EPS 1e-7f

// ---------------- scratch (device globals; no allocation allowed) ----------------
__device__ float g_h[Nn * Hh];      // node state h (residual stream)
__device__ float g_u[Nn * Hh];      // agg + x (MLP input)
__device__ float g_r[Nn * Hh];      // relu(LN(h)) for next layer / final
__device__ float g_hid[Nn * H2];    // relu(LN(u @ W1 + b1))
__device__ float g_pooled[NG * Hh];
__device__ int   g_cnt[Nn];
__device__ int   g_rowptr[Nn + 1];
__device__ int   g_pos[Nn];
__device__ int2  g_pe[Ee];          // (edge_id, src) packed, CSR order by dst

// ---------------- small utility kernels ----------------
__global__ void fill_i32(int* p, int v, int n) {
    int i = blockIdx.x * blockDim.x + threadIdx.x;
    if (i < n) p[i] = v;
}
__global__ void fill_f32(float* p, float v, int n) {
    int i = blockIdx.x * blockDim.x + threadIdx.x;
    if (i < n) p[i] = v;
}

// ---------------- CSR build ----------------
__global__ void hist_kernel(const int* __restrict__ dst, int* cnt) {
    int e = blockIdx.x * blockDim.x + threadIdx.x;
    if (e < Ee) atomicAdd(&cnt[dst[e]], 1);
}

__global__ __launch_bounds__(1024) void scan_kernel(const int* __restrict__ cnt,
                                                    int* rowptr, int* pos) {
    __shared__ int part[1024];
    const int CH = 10;  // 1024*10 = 10240 >= Nn
    int tid = threadIdx.x;
    int base = tid * CH;
    int loc[CH];
    int s = 0;
#pragma unroll
    for (int i = 0; i < CH; i++) {
        int idx = base + i;
        int v = (idx < Nn) ? cnt[idx] : 0;
        loc[i] = s;
        s += v;
    }
    part[tid] = s;
    __syncthreads();
    for (int off = 1; off < 1024; off <<= 1) {
        int v = (tid >= off) ? part[tid - off] : 0;
        __syncthreads();
        part[tid] += v;
        __syncthreads();
    }
    int pre = (tid > 0) ? part[tid - 1] : 0;
#pragma unroll
    for (int i = 0; i < CH; i++) {
        int idx = base + i;
        int v = pre + loc[i];
        if (idx <= Nn) rowptr[idx] = v;
        if (idx < Nn) pos[idx] = v;
    }
}

__global__ void scatter_kernel(const int* __restrict__ src, const int* __restrict__ dst,
                               int* pos, int2* pe) {
    int e = blockIdx.x * blockDim.x + threadIdx.x;
    if (e >= Ee) return;
    int d = dst[e];
    int slot = atomicAdd(&pos[d], 1);
    pe[slot] = make_int2(e, src[e]);
}

// ---------------- aggregation: max-free online scatter-softmax (warp per node) ----
// m = relu(x_j + e) + eps bounded small; t = 1 => exp(m*t) far from overflow.
__global__ void agg_kernel(const float* __restrict__ xin, const float* __restrict__ ea,
                           const int* __restrict__ rowptr, const int2* __restrict__ pe,
                           const float* __restrict__ tp, int layer, float* __restrict__ u) {
    int w = (blockIdx.x * blockDim.x + threadIdx.x) >> 5;
    if (w >= Nn) return;
    int lane = threadIdx.x & 31;
    float t = tp[layer];
    int beg = rowptr[w], end = rowptr[w + 1];
    int f = lane * 4;
    float Sx = 0.f, Sy = 0.f, Sz = 0.f, Sw = 0.f;
    float Ax = 0.f, Ay = 0.f, Az = 0.f, Aw = 0.f;
#pragma unroll 2
    for (int j = beg; j < end; j++) {
        int2 p = __ldg(&pe[j]);
        float4 e4 = __ldg(reinterpret_cast<const float4*>(ea + (size_t)p.x * Hh + f));
        float4 x4 = __ldg(reinterpret_cast<const float4*>(xin + (size_t)p.y * Hh + f));
        float mx = fmaxf(x4.x + e4.x, 0.f) + MSG_EPS;
        float my = fmaxf(x4.y + e4.y, 0.f) + MSG_EPS;
        float mz = fmaxf(x4.z + e4.z, 0.f) + MSG_EPS;
        float mw = fmaxf(x4.w + e4.w, 0.f) + MSG_EPS;
        float exx = __expf(mx * t), exy = __expf(my * t);
        float exz = __expf(mz * t), exw = __expf(mw * t);
        Sx += exx; Sy += exy; Sz += exz; Sw += exw;
        Ax = fmaf(mx, exx, Ax); Ay = fmaf(my, exy, Ay);
        Az = fmaf(mz, exz, Az); Aw = fmaf(mw, exw, Aw);
    }
    float4 xn = *reinterpret_cast<const float4*>(xin + (size_t)w * Hh + f);
    float4 o;
    if (end > beg) {
        o.x = Ax / Sx + xn.x;
        o.y = Ay / Sy + xn.y;
        o.z = Az / Sz + xn.z;
        o.w = Aw / Sw + xn.w;
    } else {
        o = xn;
    }
    *reinterpret_cast<float4*>(u + (size_t)w * Hh + f) = o;
}

// ---------------- GEMM with fused epilogues ----------------
// EPI 0: C = A@W + bias
// EPI 1: C = relu(LN(A@W + bias; g,b))       (LN over COLS=256, 2 warps/row)
// EPI 2: h = (ACC ? C : 0) + A@W + bias; C = h; Y = relu(LN(h; g,b))   (COLS=128)
// k vectorized by 4: per thread per 4-k chunk: RPT broadcast LDS.128 (A rows)
// + 4 LDS.128 (W) + 16*RPT FFMA -> ~89% FFMA issue density.
template <int K, int COLS, int RPT, int EPI, bool ACC, int THREADS>
__global__ __launch_bounds__(THREADS) void gemm_kernel(const float* __restrict__ A,
                                                       const float* __restrict__ W,
                                                       const float* __restrict__ bias,
                                                       const float* __restrict__ lng,
                                                       const float* __restrict__ lnb,
                                                       float* __restrict__ C,
                                                       float* __restrict__ Y, int nrows) {
    constexpr int CG = COLS / 4;       // column groups (4 cols each)
    constexpr int RG = THREADS / CG;   // row groups
    constexpr int RT = RG * RPT;       // rows per block tile
    extern __shared__ float sm[];
    float* sW = sm;                    // K*COLS
    float* sA = sm + K * COLS;         // RT*K, row-major
    __shared__ float red[RT][2][2];    // per-row {s,s2} per warp-half (EPI1)

    int tid = threadIdx.x;
    int row0 = blockIdx.x * RT;
    for (int i = tid; i < K * COLS / 4; i += THREADS)
        reinterpret_cast<float4*>(sW)[i] = reinterpret_cast<const float4*>(W)[i];
    for (int i = tid; i < RT * K / 4; i += THREADS) {
        int r = i / (K / 4), c = i % (K / 4);
        int row = row0 + r;
        float4 v = make_float4(0.f, 0.f, 0.f, 0.f);
        if (row < nrows) v = reinterpret_cast<const float4*>(A + (size_t)row * K)[c];
        reinterpret_cast<float4*>(sA)[i] = v;
    }
    __syncthreads();

    int cg = tid % CG, rg = tid / CG;
    float4 acc[RPT];
#pragma unroll
    for (int rr = 0; rr < RPT; rr++) acc[rr] = make_float4(0.f, 0.f, 0.f, 0.f);

#pragma unroll 2
    for (int k = 0; k < K; k += 4) {
        float4 a4[RPT];
#pragma unroll
        for (int rr = 0; rr < RPT; rr++)
            a4[rr] = *reinterpret_cast<const float4*>(&sA[(rg * RPT + rr) * K + k]);
#pragma unroll
        for (int kk = 0; kk < 4; kk++) {
            float4 w4 = *reinterpret_cast<const float4*>(&sW[(k + kk) * COLS + cg * 4]);
#pragma unroll
            for (int rr = 0; rr < RPT; rr++) {
                float a = reinterpret_cast<const float*>(&a4[rr])[kk];
                acc[rr].x = fmaf(a, w4.x, acc[rr].x);
                acc[rr].y = fmaf(a, w4.y, acc[rr].y);
                acc[rr].z = fmaf(a, w4.z, acc[rr].z);
                acc[rr].w = fmaf(a, w4.w, acc[rr].w);
            }
        }
    }

    float4 b4 = reinterpret_cast<const float4*>(bias)[cg];
#pragma unroll
    for (int rr = 0; rr < RPT; rr++) {
        acc[rr].x += b4.x; acc[rr].y += b4.y; acc[rr].z += b4.z; acc[rr].w += b4.w;
    }

    if (EPI == 0) {
#pragma unroll
        for (int rr = 0; rr < RPT; rr++) {
            int row = row0 + rg * RPT + rr;
            if (row < nrows)
                reinterpret_cast<float4*>(C + (size_t)row * COLS)[cg] = acc[rr];
        }
        return;
    }

    if (EPI == 2) {
        // residual add (h stream), then LN over COLS=128 within one warp
        float4 gv = reinterpret_cast<const float4*>(lng)[cg];
        float4 bv = reinterpret_cast<const float4*>(lnb)[cg];
#pragma unroll
        for (int rr = 0; rr < RPT; rr++) {
            int row = row0 + rg * RPT + rr;
            float4 h = acc[rr];
            if (ACC && row < nrows) {
                float4 old = reinterpret_cast<const float4*>(C + (size_t)row * COLS)[cg];
                h.x += old.x; h.y += old.y; h.z += old.z; h.w += old.w;
            }
            float s = h.x + h.y + h.z + h.w;
            float s2 = h.x * h.x + h.y * h.y + h.z * h.z + h.w * h.w;
#pragma unroll
            for (int o = 16; o > 0; o >>= 1) {
                s += __shfl_xor_sync(0xffffffffu, s, o);
                s2 += __shfl_xor_sync(0xffffffffu, s2, o);
            }
            float mu = s * (1.f / COLS);
            float var = s2 * (1.f / COLS) - mu * mu;
            float inv = rsqrtf(var + 1e-5f);
            float4 y;
            y.x = fmaxf((h.x - mu) * inv * gv.x + bv.x, 0.f);
            y.y = fmaxf((h.y - mu) * inv * gv.y + bv.y, 0.f);
            y.z = fmaxf((h.z - mu) * inv * gv.z + bv.z, 0.f);
            y.w = fmaxf((h.w - mu) * inv * gv.w + bv.w, 0.f);
            if (row < nrows) {
                reinterpret_cast<float4*>(C + (size_t)row * COLS)[cg] = h;
                reinterpret_cast<float4*>(Y + (size_t)row * COLS)[cg] = y;
            }
        }
        return;
    }

    // EPI == 1: LN over COLS=256, row spans 2 warps (CG=64)
    {
        int lane = tid & 31;
        int half = (tid >> 5) & 1;  // which warp of the rg pair
#pragma unroll
        for (int rr = 0; rr < RPT; rr++) {
            float s = acc[rr].x + acc[rr].y + acc[rr].z + acc[rr].w;
            float s2 = acc[rr].x * acc[rr].x + acc[rr].y * acc[rr].y +
                       acc[rr].z * acc[rr].z + acc[rr].w * acc[rr].w;
#pragma unroll
            for (int o = 16; o > 0; o >>= 1) {
                s += __shfl_xor_sync(0xffffffffu, s, o);
                s2 += __shfl_xor_sync(0xffffffffu, s2, o);
            }
            if (lane == 0) {
                int ri = rg * RPT + rr;
                red[ri][half][0] = s;
                red[ri][half][1] = s2;
            }
        }
        __syncthreads();
        float4 gv = reinterpret_cast<const float4*>(lng)[cg];
        float4 bv = reinterpret_cast<const float4*>(lnb)[cg];
#pragma unroll
        for (int rr = 0; rr < RPT; rr++) {
            int ri = rg * RPT + rr;
            float s = red[ri][0][0] + red[ri][1][0];
            float s2 = red[ri][0][1] + red[ri][1][1];
            float mu = s * (1.f / COLS);
            float var = s2 * (1.f / COLS) - mu * mu;
            float inv = rsqrtf(var + 1e-5f);
            float4 y;
            y.x = fmaxf((acc[rr].x - mu) * inv * gv.x + bv.x, 0.f);
            y.y = fmaxf((acc[rr].y - mu) * inv * gv.y + bv.y, 0.f);
            y.z = fmaxf((acc[rr].z - mu) * inv * gv.z + bv.z, 0.f);
            y.w = fmaxf((acc[rr].w - mu) * inv * gv.w + bv.w, 0.f);
            int row = row0 + ri;
            if (row < nrows)
                reinterpret_cast<float4*>(C + (size_t)row * COLS)[cg] = y;
        }
    }
}

// ---------------- global_add_pool ----------------
__global__ void pool_kernel(const float* __restrict__ r, const int* __restrict__ batch,
                            float* pooled) {
    int w = (blockIdx.x * blockDim.x + threadIdx.x) >> 5;
    if (w >= Nn) return;
    int lane = threadIdx.x & 31;
    int gidx = batch[w];
    float4 v = *reinterpret_cast<const float4*>(r + (size_t)w * Hh + lane * 4);
    float* dp = pooled + gidx * Hh + lane * 4;
    atomicAdd(dp + 0, v.x);
    atomicAdd(dp + 1, v.y);
    atomicAdd(dp + 2, v.z);
    atomicAdd(dp + 3, v.w);
}

// ---------------- classifier + output assembly ----------------
__global__ void final_kernel(const float* __restrict__ pooled, const float* __restrict__ linW,
                             const float* __restrict__ linb, float* __restrict__ out) {
    int idx = blockIdx.x * blockDim.x + threadIdx.x;
    int total = blockDim.x * gridDim.x;
    if (idx < NG * NC) {
        int gi = idx / NC, c = idx % NC;
        float sum = linb[c];
#pragma unroll 8
        for (int k = 0; k < Hh; k++) sum = fmaf(pooled[gi * Hh + k], linW[k * NC + c], sum);
        out[idx] = sum;
    }
    for (int i = idx; i < NG * Hh; i += total) out[NG * NC + i] = pooled[i];
}

// ---------------- launch ----------------
extern "C" void kernel_launch(void* const* d_in, const int* in_sizes, int n_in,
                              void* d_out, int out_size) {
    const float* x    = (const float*)d_in[0];
    const float* ea   = (const float*)d_in[1];
    const float* encW = (const float*)d_in[2];
    const float* encB = (const float*)d_in[3];
    const float* tp   = (const float*)d_in[4];
    const float* W1   = (const float*)d_in[5];
    const float* b1   = (const float*)d_in[6];
    const float* mg   = (const float*)d_in[7];
    const float* mb   = (const float*)d_in[8];
    const float* W2   = (const float*)d_in[9];
    const float* b2   = (const float*)d_in[10];
    const float* lg   = (const float*)d_in[11];
    const float* lb   = (const float*)d_in[12];
    const float* linW = (const float*)d_in[13];
    const float* linB = (const float*)d_in[14];
    const int*   eidx = (const int*)d_in[15];
    const int*   batch= (const int*)d_in[16];
    float* out = (float*)d_out;

    float *ph, *pu, *pr, *phid, *ppool;
    int *pcnt, *prow, *ppos;
    int2* ppe;
    cudaGetSymbolAddress((void**)&ph, g_h);
    cudaGetSymbolAddress((void**)&pu, g_u);
    cudaGetSymbolAddress((void**)&pr, g_r);
    cudaGetSymbolAddress((void**)&phid, g_hid);
    cudaGetSymbolAddress((void**)&ppool, g_pooled);
    cudaGetSymbolAddress((void**)&pcnt, g_cnt);
    cudaGetSymbolAddress((void**)&prow, g_rowptr);
    cudaGetSymbolAddress((void**)&ppos, g_pos);
    cudaGetSymbolAddress((void**)&ppe, g_pe);

    // Tile geometry:
    //  enc: K=128, COLS=128, THREADS=544, RPT=4 -> RT=68, grid=148 (single wave)
    //  g1 : K=128, COLS=256, THREADS=512, RPT=9 -> RT=72, grid=139 (single wave)
    //  g2 : K=256, COLS=128, THREADS=544, RPT=4 -> RT=68, grid=148 (single wave)
    const int smem_enc = (128 * 128 + 68 * 128) * 4;   // 100352
    const int smem_g1  = (128 * 256 + 72 * 128) * 4;   // 167936
    const int smem_g2  = (256 * 128 + 68 * 256) * 4;   // 200704
    cudaFuncSetAttribute((const void*)gemm_kernel<128, 128, 4, 0, false, 544>,
                         cudaFuncAttributeMaxDynamicSharedMemorySize, smem_enc);
    cudaFuncSetAttribute((const void*)gemm_kernel<128, 256, 9, 1, false, 512>,
                         cudaFuncAttributeMaxDynamicSharedMemorySize, smem_g1);
    cudaFuncSetAttribute((const void*)gemm_kernel<256, 128, 4, 2, false, 544>,
                         cudaFuncAttributeMaxDynamicSharedMemorySize, smem_g2);
    cudaFuncSetAttribute((const void*)gemm_kernel<256, 128, 4, 2, true, 544>,
                         cudaFuncAttributeMaxDynamicSharedMemorySize, smem_g2);

    const int* srcp = eidx;
    const int* dstp = eidx + Ee;
    const int G128 = (Nn + 67) / 68;   // 148
    const int G256 = (Nn + 71) / 72;   // 139

    // CSR build (by destination node)
    fill_i32<<<(Nn + 255) / 256, 256>>>(pcnt, 0, Nn);
    hist_kernel<<<(Ee + 255) / 256, 256>>>(dstp, pcnt);
    scan_kernel<<<1, 1024>>>(pcnt, prow, ppos);
    scatter_kernel<<<(Ee + 255) / 256, 256>>>(srcp, dstp, ppos, ppe);

    // encoder: h = x @ encW + encB
    gemm_kernel<128, 128, 4, 0, false, 544><<<G128, 544, smem_enc>>>(
        x, encW, encB, nullptr, nullptr, ph, nullptr, Nn);

    for (int i = 0; i < Lh; i++) {
        const float* xin = (i == 0) ? ph : pr;
        agg_kernel<<<1250, 256>>>(xin, ea, prow, ppe, tp, i, pu);
        // hid = relu(LN(u @ W1 + b1))
        gemm_kernel<128, 256, 9, 1, false, 512><<<G256, 512, smem_g1>>>(
            pu, W1 + (size_t)i * Hh * H2, b1 + (size_t)i * H2,
            mg + (size_t)i * H2, mb + (size_t)i * H2, phid, nullptr, Nn);
        // h (+)= hid @ W2 + b2 ; r = relu(LN(h; next layer's params))
        int nl = (i < Lh - 1) ? (i + 1) : 0;
        if (i == 0)
            gemm_kernel<256, 128, 4, 2, false, 544><<<G128, 544, smem_g2>>>(
                phid, W2 + (size_t)i * H2 * Hh, b2 + (size_t)i * Hh,
                lg + (size_t)nl * Hh, lb + (size_t)nl * Hh, ph, pr, Nn);
        else
            gemm_kernel<256, 128, 4, 2, true, 544><<<G128, 544, smem_g2>>>(
                phid, W2 + (size_t)i * H2 * Hh, b2 + (size_t)i * Hh,
                lg + (size_t)nl * Hh, lb + (size_t)nl * Hh, ph, pr, Nn);
    }

    // pr already holds relu(LN(h; lg[0], lb[0]))
    fill_f32<<<(NG * Hh + 255) / 256, 256>>>(ppool, 0.f, NG * Hh);
    pool_kernel<<<1250, 256>>>(pr, batch, ppool);
    final_kernel<<<36, 256>>>(ppool, linW, linB, out);
}

// round 5
// speedup vs baseline: 1.5315x; 1.0489x over previous
#include <cuda_runtime.h>
#include <cuda_fp16.h>
#include <math.h>

// Problem constants (fixed shapes)
#define Nn 10000
#define Ee 320000
#define Hh 128
#define H2 256
#define Lh 4
#define NG 64
#define NC 10
#define MSG_EPS 1e-7f

// ---------------- scratch (device globals; no allocation allowed) ----------------
__device__ float g_h[Nn * Hh];      // node state h (residual stream)
__device__ float g_u[Nn * Hh];      // agg + x (MLP input)
__device__ float g_r[Nn * Hh];      // relu(LN(h)) for next layer / final
__device__ float g_hid[Nn * H2];    // relu(LN(u @ W1 + b1))
__device__ float g_pooled[NG * Hh];
__device__ int   g_cnt[Nn];
__device__ int   g_rowptr[Nn + 1];
__device__ int   g_pos[Nn];
__device__ int2  g_pe[Ee];          // (edge_id, src) packed, CSR order by dst
__device__ int   g_psrc[Ee];        // src only, CSR order
__device__ __half2 g_eah[(size_t)Ee * 64];  // edge_attr fp16, CSR order (82 MB)

// ---------------- small utility kernels ----------------
__global__ void fill_i32(int* p, int v, int n) {
    int i = blockIdx.x * blockDim.x + threadIdx.x;
    if (i < n) p[i] = v;
}
__global__ void fill_f32(float* p, float v, int n) {
    int i = blockIdx.x * blockDim.x + threadIdx.x;
    if (i < n) p[i] = v;
}

// ---------------- CSR build ----------------
__global__ void hist_kernel(const int* __restrict__ dst, int* cnt) {
    int e = blockIdx.x * blockDim.x + threadIdx.x;
    if (e < Ee) atomicAdd(&cnt[dst[e]], 1);
}

__global__ __launch_bounds__(1024) void scan_kernel(const int* __restrict__ cnt,
                                                    int* rowptr, int* pos) {
    __shared__ int part[1024];
    const int CH = 10;  // 1024*10 = 10240 >= Nn
    int tid = threadIdx.x;
    int base = tid * CH;
    int loc[CH];
    int s = 0;
#pragma unroll
    for (int i = 0; i < CH; i++) {
        int idx = base + i;
        int v = (idx < Nn) ? cnt[idx] : 0;
        loc[i] = s;
        s += v;
    }
    part[tid] = s;
    __syncthreads();
    for (int off = 1; off < 1024; off <<= 1) {
        int v = (tid >= off) ? part[tid - off] : 0;
        __syncthreads();
        part[tid] += v;
        __syncthreads();
    }
    int pre = (tid > 0) ? part[tid - 1] : 0;
#pragma unroll
    for (int i = 0; i < CH; i++) {
        int idx = base + i;
        int v = pre + loc[i];
        if (idx <= Nn) rowptr[idx] = v;
        if (idx < Nn) pos[idx] = v;
    }
}

__global__ void scatter_kernel(const int* __restrict__ src, const int* __restrict__ dst,
                               int* pos, int2* pe) {
    int e = blockIdx.x * blockDim.x + threadIdx.x;
    if (e >= Ee) return;
    int d = dst[e];
    int slot = atomicAdd(&pos[d], 1);
    pe[slot] = make_int2(e, src[e]);
}

// edge_attr -> fp16 in CSR order; also strip src indices (warp per edge)
__global__ void eaprep_kernel(const float* __restrict__ ea, const int2* __restrict__ pe,
                              __half2* __restrict__ eah, int* __restrict__ psrc) {
    int j = (blockIdx.x * blockDim.x + threadIdx.x) >> 5;
    if (j >= Ee) return;
    int lane = threadIdx.x & 31;
    int2 p = __ldg(&pe[j]);
    if (lane == 0) psrc[j] = p.y;
    float4 v = __ldg(reinterpret_cast<const float4*>(ea + (size_t)p.x * Hh) + lane);
    eah[(size_t)j * 64 + lane * 2]     = __floats2half2_rn(v.x, v.y);
    eah[(size_t)j * 64 + lane * 2 + 1] = __floats2half2_rn(v.z, v.w);
}

// ---------------- aggregation: max-free online scatter-softmax (warp per node) ----
// m = relu(x_j + e) + eps bounded small; t = 1 => exp(m*t) far from overflow.
// edge_attr streamed sequentially as fp16 (CSR order), src as flat int array.
__global__ void agg_kernel(const float* __restrict__ xin, const __half2* __restrict__ eah,
                           const int* __restrict__ rowptr, const int* __restrict__ psrc,
                           const float* __restrict__ tp, int layer, float* __restrict__ u) {
    int w = (blockIdx.x * blockDim.x + threadIdx.x) >> 5;
    if (w >= Nn) return;
    int lane = threadIdx.x & 31;
    float t = tp[layer];
    int beg = rowptr[w], end = rowptr[w + 1];
    float Sx = 0.f, Sy = 0.f, Sz = 0.f, Sw = 0.f;
    float Ax = 0.f, Ay = 0.f, Az = 0.f, Aw = 0.f;
#pragma unroll 2
    for (int j = beg; j < end; j++) {
        int s = __ldg(&psrc[j]);
        uint2 eu = __ldg(reinterpret_cast<const uint2*>(eah + (size_t)j * 64) + lane);
        float2 e01 = __half22float2(*reinterpret_cast<__half2*>(&eu.x));
        float2 e23 = __half22float2(*reinterpret_cast<__half2*>(&eu.y));
        float4 x4 = __ldg(reinterpret_cast<const float4*>(xin + (size_t)s * Hh) + lane);
        float mx = fmaxf(x4.x + e01.x, 0.f) + MSG_EPS;
        float my = fmaxf(x4.y + e01.y, 0.f) + MSG_EPS;
        float mz = fmaxf(x4.z + e23.x, 0.f) + MSG_EPS;
        float mw = fmaxf(x4.w + e23.y, 0.f) + MSG_EPS;
        float exx = __expf(mx * t), exy = __expf(my * t);
        float exz = __expf(mz * t), exw = __expf(mw * t);
        Sx += exx; Sy += exy; Sz += exz; Sw += exw;
        Ax = fmaf(mx, exx, Ax); Ay = fmaf(my, exy, Ay);
        Az = fmaf(mz, exz, Az); Aw = fmaf(mw, exw, Aw);
    }
    float4 xn = *(reinterpret_cast<const float4*>(xin + (size_t)w * Hh) + lane);
    float4 o;
    if (end > beg) {
        o.x = Ax / Sx + xn.x;
        o.y = Ay / Sy + xn.y;
        o.z = Az / Sz + xn.z;
        o.w = Aw / Sw + xn.w;
    } else {
        o = xn;
    }
    *(reinterpret_cast<float4*>(u + (size_t)w * Hh) + lane) = o;
}

// ---------------- GEMM with fused epilogues ----------------
// EPI 0: C = A@W + bias
// EPI 1: C = relu(LN(A@W + bias; g,b))       (LN over COLS=256, 2 warps/row)
// EPI 2: h = (ACC ? C : 0) + A@W + bias; C = h; Y = relu(LN(h; g,b))   (COLS=128)
// k vectorized by 4: per thread per 4-k chunk: RPT broadcast LDS.128 (A rows)
// + 4 LDS.128 (W) + 16*RPT FFMA -> ~89% FFMA issue density.
template <int K, int COLS, int RPT, int EPI, bool ACC, int THREADS>
__global__ __launch_bounds__(THREADS) void gemm_kernel(const float* __restrict__ A,
                                                       const float* __restrict__ W,
                                                       const float* __restrict__ bias,
                                                       const float* __restrict__ lng,
                                                       const float* __restrict__ lnb,
                                                       float* __restrict__ C,
                                                       float* __restrict__ Y, int nrows) {
    constexpr int CG = COLS / 4;       // column groups (4 cols each)
    constexpr int RG = THREADS / CG;   // row groups
    constexpr int RT = RG * RPT;       // rows per block tile
    extern __shared__ float sm[];
    float* sW = sm;                    // K*COLS
    float* sA = sm + K * COLS;         // RT*K, row-major
    __shared__ float red[RT][2][2];    // per-row {s,s2} per warp-half (EPI1)

    int tid = threadIdx.x;
    int row0 = blockIdx.x * RT;
    for (int i = tid; i < K * COLS / 4; i += THREADS)
        reinterpret_cast<float4*>(sW)[i] = reinterpret_cast<const float4*>(W)[i];
    for (int i = tid; i < RT * K / 4; i += THREADS) {
        int r = i / (K / 4), c = i % (K / 4);
        int row = row0 + r;
        float4 v = make_float4(0.f, 0.f, 0.f, 0.f);
        if (row < nrows) v = reinterpret_cast<const float4*>(A + (size_t)row * K)[c];
        reinterpret_cast<float4*>(sA)[i] = v;
    }
    __syncthreads();

    int cg = tid % CG, rg = tid / CG;
    float4 acc[RPT];
#pragma unroll
    for (int rr = 0; rr < RPT; rr++) acc[rr] = make_float4(0.f, 0.f, 0.f, 0.f);

#pragma unroll 2
    for (int k = 0; k < K; k += 4) {
        float4 a4[RPT];
#pragma unroll
        for (int rr = 0; rr < RPT; rr++)
            a4[rr] = *reinterpret_cast<const float4*>(&sA[(rg * RPT + rr) * K + k]);
#pragma unroll
        for (int kk = 0; kk < 4; kk++) {
            float4 w4 = *reinterpret_cast<const float4*>(&sW[(k + kk) * COLS + cg * 4]);
#pragma unroll
            for (int rr = 0; rr < RPT; rr++) {
                float a = reinterpret_cast<const float*>(&a4[rr])[kk];
                acc[rr].x = fmaf(a, w4.x, acc[rr].x);
                acc[rr].y = fmaf(a, w4.y, acc[rr].y);
                acc[rr].z = fmaf(a, w4.z, acc[rr].z);
                acc[rr].w = fmaf(a, w4.w, acc[rr].w);
            }
        }
    }

    float4 b4 = reinterpret_cast<const float4*>(bias)[cg];
#pragma unroll
    for (int rr = 0; rr < RPT; rr++) {
        acc[rr].x += b4.x; acc[rr].y += b4.y; acc[rr].z += b4.z; acc[rr].w += b4.w;
    }

    if (EPI == 0) {
#pragma unroll
        for (int rr = 0; rr < RPT; rr++) {
            int row = row0 + rg * RPT + rr;
            if (row < nrows)
                reinterpret_cast<float4*>(C + (size_t)row * COLS)[cg] = acc[rr];
        }
        return;
    }

    if (EPI == 2) {
        // residual add (h stream), then LN over COLS=128 within one warp
        float4 gv = reinterpret_cast<const float4*>(lng)[cg];
        float4 bv = reinterpret_cast<const float4*>(lnb)[cg];
#pragma unroll
        for (int rr = 0; rr < RPT; rr++) {
            int row = row0 + rg * RPT + rr;
            float4 h = acc[rr];
            if (ACC && row < nrows) {
                float4 old = reinterpret_cast<const float4*>(C + (size_t)row * COLS)[cg];
                h.x += old.x; h.y += old.y; h.z += old.z; h.w += old.w;
            }
            float s = h.x + h.y + h.z + h.w;
            float s2 = h.x * h.x + h.y * h.y + h.z * h.z + h.w * h.w;
#pragma unroll
            for (int o = 16; o > 0; o >>= 1) {
                s += __shfl_xor_sync(0xffffffffu, s, o);
                s2 += __shfl_xor_sync(0xffffffffu, s2, o);
            }
            float mu = s * (1.f / COLS);
            float var = s2 * (1.f / COLS) - mu * mu;
            float inv = rsqrtf(var + 1e-5f);
            float4 y;
            y.x = fmaxf((h.x - mu) * inv * gv.x + bv.x, 0.f);
            y.y = fmaxf((h.y - mu) * inv * gv.y + bv.y, 0.f);
            y.z = fmaxf((h.z - mu) * inv * gv.z + bv.z, 0.f);
            y.w = fmaxf((h.w - mu) * inv * gv.w + bv.w, 0.f);
            if (row < nrows) {
                reinterpret_cast<float4*>(C + (size_t)row * COLS)[cg] = h;
                reinterpret_cast<float4*>(Y + (size_t)row * COLS)[cg] = y;
            }
        }
        return;
    }

    // EPI == 1: LN over COLS=256, row spans 2 warps (CG=64)
    {
        int lane = tid & 31;
        int half = (tid >> 5) & 1;  // which warp of the rg pair
#pragma unroll
        for (int rr = 0; rr < RPT; rr++) {
            float s = acc[rr].x + acc[rr].y + acc[rr].z + acc[rr].w;
            float s2 = acc[rr].x * acc[rr].x + acc[rr].y * acc[rr].y +
                       acc[rr].z * acc[rr].z + acc[rr].w * acc[rr].w;
#pragma unroll
            for (int o = 16; o > 0; o >>= 1) {
                s += __shfl_xor_sync(0xffffffffu, s, o);
                s2 += __shfl_xor_sync(0xffffffffu, s2, o);
            }
            if (lane == 0) {
                int ri = rg * RPT + rr;
                red[ri][half][0] = s;
                red[ri][half][1] = s2;
            }
        }
        __syncthreads();
        float4 gv = reinterpret_cast<const float4*>(lng)[cg];
        float4 bv = reinterpret_cast<const float4*>(lnb)[cg];
#pragma unroll
        for (int rr = 0; rr < RPT; rr++) {
            int ri = rg * RPT + rr;
            float s = red[ri][0][0] + red[ri][1][0];
            float s2 = red[ri][0][1] + red[ri][1][1];
            float mu = s * (1.f / COLS);
            float var = s2 * (1.f / COLS) - mu * mu;
            float inv = rsqrtf(var + 1e-5f);
            float4 y;
            y.x = fmaxf((acc[rr].x - mu) * inv * gv.x + bv.x, 0.f);
            y.y = fmaxf((acc[rr].y - mu) * inv * gv.y + bv.y, 0.f);
            y.z = fmaxf((acc[rr].z - mu) * inv * gv.z + bv.z, 0.f);
            y.w = fmaxf((acc[rr].w - mu) * inv * gv.w + bv.w, 0.f);
            int row = row0 + ri;
            if (row < nrows)
                reinterpret_cast<float4*>(C + (size_t)row * COLS)[cg] = y;
        }
    }
}

// ---------------- global_add_pool ----------------
__global__ void pool_kernel(const float* __restrict__ r, const int* __restrict__ batch,
                            float* pooled) {
    int w = (blockIdx.x * blockDim.x + threadIdx.x) >> 5;
    if (w >= Nn) return;
    int lane = threadIdx.x & 31;
    int gidx = batch[w];
    float4 v = *(reinterpret_cast<const float4*>(r + (size_t)w * Hh) + lane);
    float* dp = pooled + gidx * Hh + lane * 4;
    atomicAdd(dp + 0, v.x);
    atomicAdd(dp + 1, v.y);
    atomicAdd(dp + 2, v.z);
    atomicAdd(dp + 3, v.w);
}

// ---------------- classifier + output assembly ----------------
__global__ void final_kernel(const float* __restrict__ pooled, const float* __restrict__ linW,
                             const float* __restrict__ linb, float* __restrict__ out) {
    int idx = blockIdx.x * blockDim.x + threadIdx.x;
    int total = blockDim.x * gridDim.x;
    if (idx < NG * NC) {
        int gi = idx / NC, c = idx % NC;
        float sum = linb[c];
#pragma unroll 8
        for (int k = 0; k < Hh; k++) sum = fmaf(pooled[gi * Hh + k], linW[k * NC + c], sum);
        out[idx] = sum;
    }
    for (int i = idx; i < NG * Hh; i += total) out[NG * NC + i] = pooled[i];
}

// ---------------- launch ----------------
extern "C" void kernel_launch(void* const* d_in, const int* in_sizes, int n_in,
                              void* d_out, int out_size) {
    const float* x    = (const float*)d_in[0];
    const float* ea   = (const float*)d_in[1];
    const float* encW = (const float*)d_in[2];
    const float* encB = (const float*)d_in[3];
    const float* tp   = (const float*)d_in[4];
    const float* W1   = (const float*)d_in[5];
    const float* b1   = (const float*)d_in[6];
    const float* mg   = (const float*)d_in[7];
    const float* mb   = (const float*)d_in[8];
    const float* W2   = (const float*)d_in[9];
    const float* b2   = (const float*)d_in[10];
    const float* lg   = (const float*)d_in[11];
    const float* lb   = (const float*)d_in[12];
    const float* linW = (const float*)d_in[13];
    const float* linB = (const float*)d_in[14];
    const int*   eidx = (const int*)d_in[15];
    const int*   batch= (const int*)d_in[16];
    float* out = (float*)d_out;

    float *ph, *pu, *pr, *phid, *ppool;
    int *pcnt, *prow, *ppos, *ppsrc;
    int2* ppe;
    __half2* peah;
    cudaGetSymbolAddress((void**)&ph, g_h);
    cudaGetSymbolAddress((void**)&pu, g_u);
    cudaGetSymbolAddress((void**)&pr, g_r);
    cudaGetSymbolAddress((void**)&phid, g_hid);
    cudaGetSymbolAddress((void**)&ppool, g_pooled);
    cudaGetSymbolAddress((void**)&pcnt, g_cnt);
    cudaGetSymbolAddress((void**)&prow, g_rowptr);
    cudaGetSymbolAddress((void**)&ppos, g_pos);
    cudaGetSymbolAddress((void**)&ppsrc, g_psrc);
    cudaGetSymbolAddress((void**)&ppe, g_pe);
    cudaGetSymbolAddress((void**)&peah, g_eah);

    // Tile geometry:
    //  enc: K=128, COLS=128, THREADS=544, RPT=4 -> RT=68, grid=148 (single wave)
    //  g1 : K=128, COLS=256, THREADS=512, RPT=9 -> RT=72, grid=139 (single wave)
    //  g2 : K=256, COLS=128, THREADS=544, RPT=4 -> RT=68, grid=148 (single wave)
    const int smem_enc = (128 * 128 + 68 * 128) * 4;   // 100352
    const int smem_g1  = (128 * 256 + 72 * 128) * 4;   // 167936
    const int smem_g2  = (256 * 128 + 68 * 256) * 4;   // 200704
    cudaFuncSetAttribute((const void*)gemm_kernel<128, 128, 4, 0, false, 544>,
                         cudaFuncAttributeMaxDynamicSharedMemorySize, smem_enc);
    cudaFuncSetAttribute((const void*)gemm_kernel<128, 256, 9, 1, false, 512>,
                         cudaFuncAttributeMaxDynamicSharedMemorySize, smem_g1);
    cudaFuncSetAttribute((const void*)gemm_kernel<256, 128, 4, 2, false, 544>,
                         cudaFuncAttributeMaxDynamicSharedMemorySize, smem_g2);
    cudaFuncSetAttribute((const void*)gemm_kernel<256, 128, 4, 2, true, 544>,
                         cudaFuncAttributeMaxDynamicSharedMemorySize, smem_g2);

    const int* srcp = eidx;
    const int* dstp = eidx + Ee;
    const int G128 = (Nn + 67) / 68;   // 148
    const int G256 = (Nn + 71) / 72;   // 139

    // CSR build (by destination node) + edge_attr fp16 reorder
    fill_i32<<<(Nn + 255) / 256, 256>>>(pcnt, 0, Nn);
    hist_kernel<<<(Ee + 255) / 256, 256>>>(dstp, pcnt);
    scan_kernel<<<1, 1024>>>(pcnt, prow, ppos);
    scatter_kernel<<<(Ee + 255) / 256, 256>>>(srcp, dstp, ppos, ppe);
    eaprep_kernel<<<Ee / 8, 256>>>(ea, ppe, peah, ppsrc);

    // encoder: h = x @ encW + encB
    gemm_kernel<128, 128, 4, 0, false, 544><<<G128, 544, smem_enc>>>(
        x, encW, encB, nullptr, nullptr, ph, nullptr, Nn);

    for (int i = 0; i < Lh; i++) {
        const float* xin = (i == 0) ? ph : pr;
        agg_kernel<<<1250, 256>>>(xin, peah, prow, ppsrc, tp, i, pu);
        // hid = relu(LN(u @ W1 + b1))
        gemm_kernel<128, 256, 9, 1, false, 512><<<G256, 512, smem_g1>>>(
            pu, W1 + (size_t)i * Hh * H2, b1 + (size_t)i * H2,
            mg + (size_t)i * H2, mb + (size_t)i * H2, phid, nullptr, Nn);
        // h (+)= hid @ W2 + b2 ; r = relu(LN(h; next layer's params))
        int nl = (i < Lh - 1) ? (i + 1) : 0;
        if (i == 0)
            gemm_kernel<256, 128, 4, 2, false, 544><<<G128, 544, smem_g2>>>(
                phid, W2 + (size_t)i * H2 * Hh, b2 + (size_t)i * Hh,
                lg + (size_t)nl * Hh, lb + (size_t)nl * Hh, ph, pr, Nn);
        else
            gemm_kernel<256, 128, 4, 2, true, 544><<<G128, 544, smem_g2>>>(
                phid, W2 + (size_t)i * H2 * Hh, b2 + (size_t)i * Hh,
                lg + (size_t)nl * Hh, lb + (size_t)nl * Hh, ph, pr, Nn);
    }

    // pr already holds relu(LN(h; lg[0], lb[0]))
    fill_f32<<<(NG * Hh + 255) / 256, 256>>>(ppool, 0.f, NG * Hh);
    pool_kernel<<<1250, 256>>>(pr, batch, ppool);
    final_kernel<<<36, 256>>>(ppool, linW, linB, out);
}